// round 1
// baseline (speedup 1.0000x reference)
#include <cuda_runtime.h>

// EmbeddingRowAdapter: out[t,:] = E[ids[t],:] + (pos[ids[t]]>=0 ? A[pos]·B^T : 0)
// V=100000, D=256, M=8192, R=32, tokens = B_SZ*L = 204800

constexpr int D = 256;
constexpr int R = 32;
constexpr int DPAD = D + 8;          // 264 floats per shared row: LDS.128 reads conflict-free
constexpr int V_MAX = 100000;

__device__ int g_pos[V_MAX];
__device__ int g_is64;               // 1 if ids/idx are int64, 0 if int32

// --- detect int32 vs int64 storage of the index arrays -----------------
// idx is arange(M). int64 little-endian read as int32 -> [0,0,1,0,2,0,...]
// so word[1]==0 means int64; int32 -> word[1]==1.
__global__ void detect_dtype_kernel(const int* idx_words, int M) {
    if (threadIdx.x == 0 && blockIdx.x == 0) {
        g_is64 = (M > 1 && idx_words[1] == 0) ? 1 : 0;
    }
}

__global__ void init_pos_kernel(int V) {
    int i = blockIdx.x * blockDim.x + threadIdx.x;
    if (i < V) g_pos[i] = -1;
}

__global__ void scatter_pos_kernel(const void* __restrict__ idx, int M) {
    int i = blockIdx.x * blockDim.x + threadIdx.x;
    if (i < M) {
        long long v;
        if (g_is64) v = ((const long long*)idx)[i];
        else        v = ((const int*)idx)[i];
        if (v >= 0 && v < V_MAX) g_pos[v] = i;
    }
}

// --- main kernel: one warp per token ------------------------------------
__global__ __launch_bounds__(256, 7)
void adapter_kernel(const void* __restrict__ ids,
                    const float* __restrict__ E,
                    const float* __restrict__ A,
                    const float* __restrict__ Bm,   // [D, R] row-major
                    float* __restrict__ out,
                    int n_tokens)
{
    __shared__ float Bt[R][DPAD];    // transposed B: Bt[r][d] = Bm[d*R + r]
    // Cooperative transpose-load. Global reads coalesced (consecutive i).
    // Scalar STS has 4-way bank conflicts (one-time, hidden under mainloop).
    for (int i = threadIdx.x; i < D * R; i += blockDim.x) {
        int d = i >> 5;              // i / R
        int r = i & 31;              // i % R
        Bt[r][d] = Bm[i];
    }
    __syncthreads();

    const int lane   = threadIdx.x & 31;
    const int warp   = (blockIdx.x * blockDim.x + threadIdx.x) >> 5;
    const int nwarps = (gridDim.x * blockDim.x) >> 5;
    const int is64   = g_is64;

    for (int t = warp; t < n_tokens; t += nwarps) {
        long long id;
        if (is64) id = ((const long long*)ids)[t];
        else      id = ((const int*)ids)[t];

        const float4* erow = reinterpret_cast<const float4*>(E + (size_t)id * D);
        // lane covers d = [4*lane, 4*lane+4) and [128 + 4*lane, ...): both
        // reads/stores are fully coalesced 128B transactions per warp.
        float4 v0 = erow[lane];
        float4 v1 = erow[lane + 32];

        int p = g_pos[id];           // warp-uniform
        if (p >= 0) {
            // Broadcast-load the 32-float A row into registers (L1 broadcast).
            float a[R];
            const float4* arow = reinterpret_cast<const float4*>(A + (size_t)p * R);
#pragma unroll
            for (int j = 0; j < R / 4; j++) {
                float4 av = __ldg(&arow[j]);
                a[4*j+0] = av.x; a[4*j+1] = av.y;
                a[4*j+2] = av.z; a[4*j+3] = av.w;
            }
            float4 acc0 = make_float4(0.f, 0.f, 0.f, 0.f);
            float4 acc1 = make_float4(0.f, 0.f, 0.f, 0.f);
#pragma unroll
            for (int r = 0; r < R; r++) {
                float4 b0 = *reinterpret_cast<const float4*>(&Bt[r][4 * lane]);
                float4 b1 = *reinterpret_cast<const float4*>(&Bt[r][128 + 4 * lane]);
                acc0.x = fmaf(a[r], b0.x, acc0.x);
                acc0.y = fmaf(a[r], b0.y, acc0.y);
                acc0.z = fmaf(a[r], b0.z, acc0.z);
                acc0.w = fmaf(a[r], b0.w, acc0.w);
                acc1.x = fmaf(a[r], b1.x, acc1.x);
                acc1.y = fmaf(a[r], b1.y, acc1.y);
                acc1.z = fmaf(a[r], b1.z, acc1.z);
                acc1.w = fmaf(a[r], b1.w, acc1.w);
            }
            v0.x += acc0.x; v0.y += acc0.y; v0.z += acc0.z; v0.w += acc0.w;
            v1.x += acc1.x; v1.y += acc1.y; v1.z += acc1.z; v1.w += acc1.w;
        }

        float4* orow = reinterpret_cast<float4*>(out + (size_t)t * D);
        orow[lane]      = v0;
        orow[lane + 32] = v1;
    }
}

extern "C" void kernel_launch(void* const* d_in, const int* in_sizes, int n_in,
                              void* d_out, int out_size)
{
    const void*  ids = d_in[0];                       // [B,L] int32 or int64
    const void*  idx = d_in[1];                       // [M]   int32 or int64
    const float* E   = (const float*)d_in[2];         // [V,D]
    const float* A   = (const float*)d_in[3];         // [M,R]
    const float* Bm  = (const float*)d_in[4];         // [D,R]
    float*       out = (float*)d_out;

    const int n_tokens = in_sizes[0];
    const int M        = in_sizes[1];
    const int V        = in_sizes[2] / D;

    detect_dtype_kernel<<<1, 32>>>((const int*)idx, M);
    init_pos_kernel<<<(V + 255) / 256, 256>>>(V);
    scatter_pos_kernel<<<(M + 255) / 256, 256>>>(idx, M);

    // 2048 blocks x 8 warps = 16384 warps, ~12.5 tokens each.
    adapter_kernel<<<2048, 256>>>(ids, E, A, Bm, out, n_tokens);
}

// round 2
// speedup vs baseline: 1.5415x; 1.5415x over previous
#include <cuda_runtime.h>

// EmbeddingRowAdapter: out[t,:] = E[ids[t],:] + (pos[ids[t]]>=0 ? A[pos]·B^T : 0)
// V=100000, D=256, M=8192, R=32, tokens = 204800

constexpr int D = 256;
constexpr int R = 32;
constexpr int V_MAX = 100000;

__device__ int   g_pos[V_MAX];
__device__ int   g_is64;            // 1 if ids/idx stored as int64, 0 if int32
__device__ float g_Bt[R][D];        // B transposed: g_Bt[r][d] = Bm[d*R + r]

// idx is arange(M): int64 little-endian read as int32 -> word[1]==0; int32 -> 1.
__global__ void detect_dtype_kernel(const int* idx_words, int M) {
    if (threadIdx.x == 0 && blockIdx.x == 0)
        g_is64 = (M > 1 && idx_words[1] == 0) ? 1 : 0;
}

__global__ void init_pos_kernel(int V) {
    int i = blockIdx.x * blockDim.x + threadIdx.x;
    if (i < V) g_pos[i] = -1;
}

__global__ void scatter_pos_kernel(const void* __restrict__ idx, int M) {
    int i = blockIdx.x * blockDim.x + threadIdx.x;
    if (i < M) {
        long long v = g_is64 ? ((const long long*)idx)[i]
                             : (long long)((const int*)idx)[i];
        if (v >= 0 && v < V_MAX) g_pos[v] = i;
    }
}

__global__ void transpose_b_kernel(const float* __restrict__ Bm) {
    int i = blockIdx.x * blockDim.x + threadIdx.x;   // i = d*R + r
    if (i < D * R) g_Bt[i & (R - 1)][i >> 5] = Bm[i];
}

// Add LoRA delta for one token: v += A[p,:] @ Bt[:, lane-cols]
__device__ __forceinline__ void add_delta(float4& v0, float4& v1,
                                          const float* __restrict__ A,
                                          int p, int lane) {
    const float4* arow = reinterpret_cast<const float4*>(A + (size_t)p * R);
    float4 acc0 = make_float4(0.f, 0.f, 0.f, 0.f);
    float4 acc1 = make_float4(0.f, 0.f, 0.f, 0.f);
#pragma unroll
    for (int j = 0; j < R / 4; j++) {
        float4 av = __ldg(arow + j);
        float as[4] = {av.x, av.y, av.z, av.w};
#pragma unroll
        for (int rr = 0; rr < 4; rr++) {
            int r = 4 * j + rr;
            float4 b0 = *reinterpret_cast<const float4*>(&g_Bt[r][4 * lane]);
            float4 b1 = *reinterpret_cast<const float4*>(&g_Bt[r][128 + 4 * lane]);
            acc0.x = fmaf(as[rr], b0.x, acc0.x);
            acc0.y = fmaf(as[rr], b0.y, acc0.y);
            acc0.z = fmaf(as[rr], b0.z, acc0.z);
            acc0.w = fmaf(as[rr], b0.w, acc0.w);
            acc1.x = fmaf(as[rr], b1.x, acc1.x);
            acc1.y = fmaf(as[rr], b1.y, acc1.y);
            acc1.z = fmaf(as[rr], b1.z, acc1.z);
            acc1.w = fmaf(as[rr], b1.w, acc1.w);
        }
    }
    v0.x += acc0.x; v0.y += acc0.y; v0.z += acc0.z; v0.w += acc0.w;
    v1.x += acc1.x; v1.y += acc1.y; v1.z += acc1.z; v1.w += acc1.w;
}

// One warp owns a 32-token tile. ids+pos gathered coalesced up front (lane-per-
// token, distributed via shfl); inner loop does 4 tokens/iter with all 8 E
// float4 loads issued before first use (MLP=8). Streaming stores keep E in L2.
__global__ __launch_bounds__(128, 8)
void adapter_kernel(const void* __restrict__ ids,
                    const float* __restrict__ E,
                    const float* __restrict__ A,
                    float* __restrict__ out,
                    int n_tokens)
{
    const int lane   = threadIdx.x & 31;
    const int warp   = (blockIdx.x * blockDim.x + threadIdx.x) >> 5;
    const int nwarps = (gridDim.x * blockDim.x) >> 5;
    const int is64   = g_is64;

    for (int t0 = warp * 32; t0 < n_tokens; t0 += nwarps * 32) {
        // Coalesced gather of this tile's ids and pos (one token per lane).
        int tl = t0 + lane;
        int myid = 0, mypos = -1;
        if (tl < n_tokens) {
            long long v = is64 ? ((const long long*)ids)[tl]
                               : (long long)((const int*)ids)[tl];
            myid  = (int)v;
            mypos = g_pos[myid];
        }
        const int lim = min(32, n_tokens - t0);

        for (int k = 0; k < lim; k += 4) {
            int id_[4], p_[4];
            bool have[4];
#pragma unroll
            for (int u = 0; u < 4; u++) {
                have[u] = (k + u) < lim;
                int src = (k + u) & 31;
                id_[u] = __shfl_sync(0xffffffffu, myid,  src);
                p_[u]  = __shfl_sync(0xffffffffu, mypos, src);
            }

            // Issue all E loads first: 8 independent float4 loads in flight.
            float4 v0[4], v1[4];
#pragma unroll
            for (int u = 0; u < 4; u++) {
                if (have[u]) {
                    const float4* e = reinterpret_cast<const float4*>(
                        E + (size_t)id_[u] * D);
                    v0[u] = __ldg(e + lane);
                    v1[u] = __ldg(e + 32 + lane);
                }
            }

            // Adapter delta (warp-uniform branch) + streaming store.
#pragma unroll
            for (int u = 0; u < 4; u++) {
                if (!have[u]) continue;
                if (p_[u] >= 0) add_delta(v0[u], v1[u], A, p_[u], lane);
                float4* o = reinterpret_cast<float4*>(
                    out + (size_t)(t0 + k + u) * D);
                __stcs(o + lane,      v0[u]);
                __stcs(o + 32 + lane, v1[u]);
            }
        }
    }
}

extern "C" void kernel_launch(void* const* d_in, const int* in_sizes, int n_in,
                              void* d_out, int out_size)
{
    const void*  ids = d_in[0];                 // [B,L] int32 or int64
    const void*  idx = d_in[1];                 // [M]   int32 or int64
    const float* E   = (const float*)d_in[2];   // [V,D]
    const float* A   = (const float*)d_in[3];   // [M,R]
    const float* Bm  = (const float*)d_in[4];   // [D,R]
    float*       out = (float*)d_out;

    const int n_tokens = in_sizes[0];
    const int M        = in_sizes[1];
    const int V        = in_sizes[2] / D;

    detect_dtype_kernel<<<1, 32>>>((const int*)idx, M);
    init_pos_kernel<<<(V + 255) / 256, 256>>>(V);
    scatter_pos_kernel<<<(M + 255) / 256, 256>>>(idx, M);
    transpose_b_kernel<<<(D * R + 255) / 256, 256>>>(Bm);

    // 6400 32-token tiles; 1600 blocks x 4 warps = exactly one tile per warp.
    int n_tiles  = (n_tokens + 31) / 32;
    int n_blocks = (n_tiles + 3) / 4;
    adapter_kernel<<<n_blocks, 128>>>(ids, E, A, out, n_tokens);
}